// round 8
// baseline (speedup 1.0000x reference)
#include <cuda_runtime.h>
#include <cstdint>

// EntropyCalculator: per-row histogram entropy.
//   x: [B, 64] int32, values in [0, 40)   out: [B, 1] float32
// H(row) = ln(64) - (ln2/64) * sum_v c_v * log2(c_v)
//
// Staging via cp.async.cg (LDGSTS): global->smem with no register round-trip,
// so each block's full 32 KB tile is in flight at once and DRAM streaming
// decouples from the smem histogram phase.

#define NT 128          // threads per block = rows per tile
#define NW 10           // 40 vocab bins as 4x8-bit byte counts per word

__global__ __launch_bounds__(NT, 4) void entropy_hist_kernel(
    const int4* __restrict__ x, float* __restrict__ out, int B)
{
    __shared__ uint32_t tile[NT * 64];   // raw ids, XOR-swizzled 16B granules (32 KB)
    __shared__ uint32_t h0[NW * NT];     // 4 sub-hists -> 4 independent RMW chains
    __shared__ uint32_t h1[NW * NT];
    __shared__ uint32_t h2[NW * NT];
    __shared__ uint32_t h3[NW * NT];

    const int tid = threadIdx.x;
    const uint32_t t4 = (uint32_t)tid << 2;
    unsigned char* p0 = (unsigned char*)h0;
    unsigned char* p1 = (unsigned char*)h1;
    unsigned char* p2 = (unsigned char*)h2;
    unsigned char* p3 = (unsigned char*)h3;

    #pragma unroll
    for (int i = 0; i < NW; i++) {
        h0[i * NT + tid] = 0u; h1[i * NT + tid] = 0u;
        h2[i * NT + tid] = 0u; h3[i * NT + tid] = 0u;
    }

    // ---- Stage tile with cp.async: 16 x 16B per thread, coalesced reads,
    // XOR-swizzled dst (granule j of row r lands at j ^ (r&7)) --------------
    const int row0 = blockIdx.x * NT;
    const int rows_here = min(NT, B - row0);
    const int e_limit = rows_here * 16;
    const int4* gp = x + (size_t)row0 * 16;
    uint32_t tile_b = (uint32_t)__cvta_generic_to_shared(tile);
    #pragma unroll
    for (int k = 0; k < 16; k++) {
        int e = tid + k * NT;
        if (e < e_limit) {
            int r = e >> 4, j = e & 15;
            uint32_t dst = tile_b + (uint32_t)((r << 8) + ((j ^ (r & 7)) << 4));
            asm volatile("cp.async.cg.shared.global [%0], [%1], 16;"
                         :: "r"(dst), "l"(gp + e));
        }
    }
    asm volatile("cp.async.commit_group;" ::: "memory");
    asm volatile("cp.async.wait_group 0;" ::: "memory");
    __syncthreads();

    const int row = row0 + tid;
    if (row < B) {
        // ---- Histogram own row: 16 LDS.128 (conflict-free via swizzle),
        // 64 byte-RMWs spread over 4 distinct arrays (bank = tid%32) ---------
        // NT=128 byte addr: bits [0:1]=v&3, [2:8]=tid, [9:12]=v>>2 (disjoint).
        const uint32_t trow = (uint32_t)tid << 6;   // tid * 64 words
        const uint32_t sw = (uint32_t)(tid & 7);
        #pragma unroll
        for (int j = 0; j < 16; j++) {
            uint4 q = *(const uint4*)&tile[trow + ((j ^ sw) << 2)];
            p0[(((q.x & 0x3Cu) << 7) | (q.x & 3u)) + t4]++;
            p1[(((q.y & 0x3Cu) << 7) | (q.y & 3u)) + t4]++;
            p2[(((q.z & 0x3Cu) << 7) | (q.z & 3u)) + t4]++;
            p3[(((q.w & 0x3Cu) << 7) | (q.w & 3u)) + t4]++;
        }

        // ---- Merge (byte sums <= 64: no carry crossing) + entropy ----------
        float acc = 0.0f;
        #pragma unroll
        for (int i = 0; i < NW; i++) {
            uint32_t w = h0[i * NT + tid] + h1[i * NT + tid]
                       + h2[i * NT + tid] + h3[i * NT + tid];
            #pragma unroll
            for (int b = 0; b < 4; b++) {
                float cf = (float)((w >> (8 * b)) & 0xFFu);
                acc += cf * __log2f(fmaxf(cf, 1.0f));   // c = 0,1 -> 0
            }
        }
        out[row] = 4.1588830833596718565f - acc * 0.010830424696159069f; // ln64 - acc*ln2/64
    }
}

extern "C" void kernel_launch(void* const* d_in, const int* in_sizes, int n_in,
                              void* d_out, int out_size)
{
    const int4* x = (const int4*)d_in[0];
    float* out    = (float*)d_out;
    int B = in_sizes[0] / 64;
    int grid = (B + NT - 1) / NT;
    entropy_hist_kernel<<<grid, NT>>>(x, out, B);
}